// round 1
// baseline (speedup 1.0000x reference)
#include <cuda_runtime.h>
#include <math.h>

#define BB 16
#define HH 12
#define NN 784
#define NSQ (NN * NN)          // 614656
#define NSQ4 (NSQ / 4)         // 153664
#define SUM_BLOCKS 64

// Device-global scratch (no allocation allowed)
__device__ int   g_bmax[BB];                 // per-batch max (float bits, nonneg)
__device__ float g_partial[BB * SUM_BLOCKS]; // per-batch partial exp-sums
__device__ float g_binv[BB];                 // per-batch 1/sum

// ---------------------------------------------------------------------------
// k_init: reset scratch
// ---------------------------------------------------------------------------
__global__ void k_init() {
    int t = threadIdx.x;
    if (t < BB) { g_bmax[t] = 0; g_binv[t] = 0.f; }
    if (t < BB * SUM_BLOCKS) g_partial[t] = 0.f;
}

// ---------------------------------------------------------------------------
// k_agg: one block per (b, i). 384 threads = 12 warps, warp w owns head w.
// Loads 12 rows (784 fp32 each) into SMEM once, computes rowsums and
// agg[l] = sum_h m[h][l] * rowsum[h]. Writes agg row to out, atomicMax batch max.
// ---------------------------------------------------------------------------
__global__ __launch_bounds__(384) void k_agg(const float* __restrict__ m,
                                             float* __restrict__ out) {
    __shared__ float sm[HH * NN];   // 37632 B
    __shared__ float rs[HH];
    __shared__ float redbuf[HH];

    const int bi = blockIdx.x;           // b*N + i
    const int b  = bi / NN;
    const int i  = bi - b * NN;
    const int w    = threadIdx.x >> 5;
    const int lane = threadIdx.x & 31;

    // warp w: load head-w row (196 float4s), accumulate rowsum
    const float4* row = (const float4*)(m + ((size_t)(b * HH + w) * NN + i) * NN);
    float4* smrow = (float4*)(sm + w * NN);
    float s = 0.f;
    #pragma unroll
    for (int j = lane; j < NN / 4; j += 32) {
        float4 v = row[j];
        smrow[j] = v;
        s += (v.x + v.y) + (v.z + v.w);
    }
    #pragma unroll
    for (int o = 16; o; o >>= 1) s += __shfl_xor_sync(0xffffffffu, s, o);
    if (lane == 0) rs[w] = s;
    __syncthreads();

    float rr[HH];
    #pragma unroll
    for (int h = 0; h < HH; h++) rr[h] = rs[h];

    float* orow = out + (size_t)bi * NN;
    float mx = 0.f;
    for (int l = threadIdx.x; l < NN; l += 384) {
        float a = 0.f;
        #pragma unroll
        for (int h = 0; h < HH; h++) a = fmaf(sm[h * NN + l], rr[h], a);
        orow[l] = a;
        mx = fmaxf(mx, a);
    }
    #pragma unroll
    for (int o = 16; o; o >>= 1) mx = fmaxf(mx, __shfl_xor_sync(0xffffffffu, mx, o));
    if (lane == 0) redbuf[w] = mx;
    __syncthreads();
    if (threadIdx.x == 0) {
        float M = redbuf[0];
        #pragma unroll
        for (int h = 1; h < HH; h++) M = fmaxf(M, redbuf[h]);
        // all values nonnegative -> int-bit compare == float compare
        atomicMax(&g_bmax[b], __float_as_int(M));
    }
}

// ---------------------------------------------------------------------------
// k_sum: per-batch sum of exp(x - max). blockIdx.y = batch.
// Deterministic: fixed element assignment + tree reduce, one partial per block.
// ---------------------------------------------------------------------------
__global__ __launch_bounds__(256) void k_sum(const float* __restrict__ out) {
    const int b = blockIdx.y;
    const float bmax = __int_as_float(g_bmax[b]);
    const float4* p = (const float4*)(out + (size_t)b * NSQ);

    float s = 0.f;
    for (int j = blockIdx.x * blockDim.x + threadIdx.x; j < NSQ4;
         j += gridDim.x * blockDim.x) {
        float4 v = p[j];
        s += expf(v.x - bmax) + expf(v.y - bmax)
           + expf(v.z - bmax) + expf(v.w - bmax);
    }
    #pragma unroll
    for (int o = 16; o; o >>= 1) s += __shfl_xor_sync(0xffffffffu, s, o);
    __shared__ float wsum[8];
    if ((threadIdx.x & 31) == 0) wsum[threadIdx.x >> 5] = s;
    __syncthreads();
    if (threadIdx.x == 0) {
        float t = 0.f;
        #pragma unroll
        for (int k = 0; k < 8; k++) t += wsum[k];
        g_partial[b * SUM_BLOCKS + blockIdx.x] = t;
    }
}

// k_sum2: reduce 64 partials per batch -> 1/sum. 16 blocks x 32 threads.
__global__ void k_sum2() {
    const int b = blockIdx.x;
    const int t = threadIdx.x;
    float s = g_partial[b * SUM_BLOCKS + 2 * t] + g_partial[b * SUM_BLOCKS + 2 * t + 1];
    #pragma unroll
    for (int o = 16; o; o >>= 1) s += __shfl_xor_sync(0xffffffffu, s, o);
    if (t == 0) g_binv[b] = 1.f / s;
}

// ---------------------------------------------------------------------------
// k_norm: out = exp(x - max[b]) / sum[b], vectorized, in place.
// Total float4s = 16 * 153664 = 2458624 = 9604 blocks * 256 threads exactly.
// ---------------------------------------------------------------------------
__global__ __launch_bounds__(256) void k_norm(float* __restrict__ out) {
    const int j = blockIdx.x * 256 + threadIdx.x;   // float4 index
    const int b = j / NSQ4;                          // same batch for all 4 lanes
    const float bmax = __int_as_float(g_bmax[b]);
    const float inv  = g_binv[b];
    float4 v = ((const float4*)out)[j];
    v.x = expf(v.x - bmax) * inv;
    v.y = expf(v.y - bmax) * inv;
    v.z = expf(v.z - bmax) * inv;
    v.w = expf(v.w - bmax) * inv;
    ((float4*)out)[j] = v;
}

// ---------------------------------------------------------------------------
extern "C" void kernel_launch(void* const* d_in, const int* in_sizes, int n_in,
                              void* d_out, int out_size) {
    const float* m = (const float*)d_in[0];
    float* out = (float*)d_out;

    k_init<<<1, 1024>>>();
    k_agg<<<BB * NN, 384>>>(m, out);
    k_sum<<<dim3(SUM_BLOCKS, BB), 256>>>(out);
    k_sum2<<<BB, 32>>>();
    k_norm<<<(BB * NSQ4) / 256, 256>>>(out);
}

// round 2
// speedup vs baseline: 1.0648x; 1.0648x over previous
#include <cuda_runtime.h>
#include <cuda_fp16.h>
#include <math.h>

#define BB 16
#define HH 12
#define NN 784
#define NROWS (BB * NN)        // 12544
#define NSQ (NN * NN)          // 614656

// Device-global scratch (allocation is forbidden; __device__ globals are allowed)
__device__ __half g_scratch[(size_t)BB * NSQ];   // exp(x - rowmax), ~19.7 MB
__device__ float2 g_rowstats[NROWS];             // (rowmax, rowsumexp)
__device__ float  g_rowscale[NROWS];             // exp(rowmax - gmax) / sum_b

// ---------------------------------------------------------------------------
// k_agg: one block per (b,i). 384 threads = 12 warps, warp w stages head w's
// row in SMEM + computes its rowsum. Then agg[l] = sum_h m[h][l]*rowsum[h] is
// held in registers (each thread owns l = t, t+384, and t<16 also t+768),
// row max + exp + row expsum computed in-block. Writes fp16 exp values and
// per-row stats. No atomics, no init needed, fully deterministic.
// ---------------------------------------------------------------------------
__global__ __launch_bounds__(384) void k_agg(const float* __restrict__ m) {
    __shared__ float sm[HH * NN];   // 37632 B
    __shared__ float rs[HH];
    __shared__ float red[HH];
    __shared__ float s_bcast;

    const int bi = blockIdx.x;          // b*NN + i
    const int b  = bi / NN;
    const int i  = bi - b * NN;
    const int t    = threadIdx.x;
    const int w    = t >> 5;
    const int lane = t & 31;

    // stage head-w row (196 float4s) + rowsum
    const float4* row = (const float4*)(m + ((size_t)(b * HH + w) * NN + i) * NN);
    float4* smrow = (float4*)(sm + w * NN);
    float s = 0.f;
    #pragma unroll
    for (int j = lane; j < NN / 4; j += 32) {
        float4 v = row[j];
        smrow[j] = v;
        s += (v.x + v.y) + (v.z + v.w);
    }
    #pragma unroll
    for (int o = 16; o; o >>= 1) s += __shfl_xor_sync(0xffffffffu, s, o);
    if (lane == 0) rs[w] = s;
    __syncthreads();

    float rr[HH];
    #pragma unroll
    for (int h = 0; h < HH; h++) rr[h] = rs[h];

    // aggregated row values in registers
    float a0 = 0.f, a1 = 0.f, a2 = 0.f;
    #pragma unroll
    for (int h = 0; h < HH; h++) {
        a0 = fmaf(sm[h * NN + t],       rr[h], a0);
        a1 = fmaf(sm[h * NN + t + 384], rr[h], a1);
    }
    if (t < 16) {
        #pragma unroll
        for (int h = 0; h < HH; h++) a2 = fmaf(sm[h * NN + t + 768], rr[h], a2);
    }

    // row max (block reduce)
    float mx = fmaxf(a0, a1);
    if (t < 16) mx = fmaxf(mx, a2);
    #pragma unroll
    for (int o = 16; o; o >>= 1) mx = fmaxf(mx, __shfl_xor_sync(0xffffffffu, mx, o));
    if (lane == 0) red[w] = mx;
    __syncthreads();
    if (t == 0) {
        float M = red[0];
        #pragma unroll
        for (int h = 1; h < HH; h++) M = fmaxf(M, red[h]);
        s_bcast = M;
    }
    __syncthreads();
    const float rowmax = s_bcast;

    // exp + fp16 store + row expsum
    __half* srow = g_scratch + (size_t)bi * NN;
    float e0 = expf(a0 - rowmax);
    float e1 = expf(a1 - rowmax);
    srow[t]       = __float2half_rn(e0);
    srow[t + 384] = __float2half_rn(e1);
    float sume = e0 + e1;
    if (t < 16) {
        float e2 = expf(a2 - rowmax);
        srow[t + 768] = __float2half_rn(e2);
        sume += e2;
    }
    #pragma unroll
    for (int o = 16; o; o >>= 1) sume += __shfl_xor_sync(0xffffffffu, sume, o);
    if (lane == 0) red[w] = sume;   // safe: t0 finished reading red before sync #2
    __syncthreads();
    if (t == 0) {
        float S = 0.f;
        #pragma unroll
        for (int h = 0; h < HH; h++) S += red[h];
        g_rowstats[bi] = make_float2(rowmax, S);
    }
}

// ---------------------------------------------------------------------------
// k_combine: one block per batch. Reduce 784 row stats -> gmax, 1/sum,
// write per-row scale. Fixed-order tree reductions -> deterministic.
// ---------------------------------------------------------------------------
__global__ __launch_bounds__(256) void k_combine() {
    const int b = blockIdx.x;
    const int t = threadIdx.x;
    __shared__ float red[8];
    __shared__ float s_gmax, s_inv;

    // phase 1: gmax
    float mx = -1e30f;
    for (int i = t; i < NN; i += 256) mx = fmaxf(mx, g_rowstats[b * NN + i].x);
    #pragma unroll
    for (int o = 16; o; o >>= 1) mx = fmaxf(mx, __shfl_xor_sync(0xffffffffu, mx, o));
    if ((t & 31) == 0) red[t >> 5] = mx;
    __syncthreads();
    if (t == 0) {
        float M = red[0];
        #pragma unroll
        for (int k = 1; k < 8; k++) M = fmaxf(M, red[k]);
        s_gmax = M;
    }
    __syncthreads();
    const float gmax = s_gmax;

    // phase 2: sum = sum_i rowsum_i * exp(rowmax_i - gmax)
    float s = 0.f;
    for (int i = t; i < NN; i += 256) {
        float2 st = g_rowstats[b * NN + i];
        s += st.y * expf(st.x - gmax);
    }
    #pragma unroll
    for (int o = 16; o; o >>= 1) s += __shfl_xor_sync(0xffffffffu, s, o);
    __syncthreads();                 // protect red[] reuse
    if ((t & 31) == 0) red[t >> 5] = s;
    __syncthreads();
    if (t == 0) {
        float S = 0.f;
        #pragma unroll
        for (int k = 0; k < 8; k++) S += red[k];
        s_inv = 1.f / S;
    }
    __syncthreads();
    const float inv = s_inv;

    // phase 3: per-row scale
    for (int i = t; i < NN; i += 256)
        g_rowscale[b * NN + i] = expf(g_rowstats[b * NN + i].x - gmax) * inv;
}

// ---------------------------------------------------------------------------
// k_norm: out[bi][l] = half2float(scratch[bi][l]) * rowscale[bi]
// Vectorized: 8 halves (uint4) in -> 2 float4 out per thread.
// Total uint4 = 16*614656/8 = 1,229,312 = 4802 blocks * 256 exactly.
// ---------------------------------------------------------------------------
__global__ __launch_bounds__(256) void k_norm(float* __restrict__ out) {
    const int j = blockIdx.x * 256 + threadIdx.x;   // uint4 index
    const int row = j / 98;                          // 98 uint4 per row (784/8)
    const float sc = g_rowscale[row];

    uint4 v = ((const uint4*)g_scratch)[j];
    float2 f0 = __half22float2(*(__half2*)&v.x);
    float2 f1 = __half22float2(*(__half2*)&v.y);
    float2 f2 = __half22float2(*(__half2*)&v.z);
    float2 f3 = __half22float2(*(__half2*)&v.w);

    float4 o0 = make_float4(f0.x * sc, f0.y * sc, f1.x * sc, f1.y * sc);
    float4 o1 = make_float4(f2.x * sc, f2.y * sc, f3.x * sc, f3.y * sc);
    ((float4*)out)[2 * j]     = o0;
    ((float4*)out)[2 * j + 1] = o1;
}

// ---------------------------------------------------------------------------
extern "C" void kernel_launch(void* const* d_in, const int* in_sizes, int n_in,
                              void* d_out, int out_size) {
    const float* m = (const float*)d_in[0];
    float* out = (float*)d_out;

    k_agg<<<BB * NN, 384>>>(m);
    k_combine<<<BB, 256>>>();
    k_norm<<<4802, 256>>>(out);
}